// round 11
// baseline (speedup 1.0000x reference)
#include <cuda_runtime.h>
#include <cuda_fp16.h>
#include <cstdint>
#include <cstddef>

#define D_MODEL 1024
#define N_HEADS 16
#define BATCH   4
#define SEQ     2048
#define DK      64
#define M_ROWS  (BATCH * SEQ)
#define BHT     (64 * SEQ * DK)

// Q pre-scale: (1/sqrt(dk)) * log2(e) so softmax uses raw ex2
#define QSCALE 0.18033688011112042f

__device__ __half g_x16[M_ROWS * D_MODEL];
__device__ __half g_w4[4 * D_MODEL * D_MODEL];
__device__ __half g_q [BHT];            // [bh][t][dk], pre-scaled by QSCALE
__device__ __half g_k [BHT];            // [bh][t][dk]
__device__ __half g_vt[BHT];            // [bh][dk][t]
__device__ __half g_o [M_ROWS * D_MODEL];

__device__ __forceinline__ uint32_t smem_u32(const void* p) {
    uint32_t a;
    asm("{ .reg .u64 t; cvta.to.shared.u64 t, %1; cvt.u32.u64 %0, t; }" : "=r"(a) : "l"(p));
    return a;
}
#define CP_ASYNC16(dst, src) \
    asm volatile("cp.async.cg.shared.global [%0], [%1], 16;" :: "r"(dst), "l"(src))
#define CP_COMMIT()  asm volatile("cp.async.commit_group;" ::: "memory")
#define CP_WAIT(n)   asm volatile("cp.async.wait_group %0;" :: "n"(n) : "memory")
#define LDMX4(r0, r1, r2, r3, addr) \
    asm volatile("ldmatrix.sync.aligned.m8n8.x4.shared.b16 {%0,%1,%2,%3}, [%4];" \
        : "=r"(r0), "=r"(r1), "=r"(r2), "=r"(r3) : "r"(addr))
#define MMA16816(acc, a0, a1, a2, a3, b0, b1) \
    asm volatile("mma.sync.aligned.m16n8k16.row.col.f32.f16.f16.f32 " \
        "{%0,%1,%2,%3},{%4,%5,%6,%7},{%8,%9},{%0,%1,%2,%3};" \
        : "+f"((acc)[0]), "+f"((acc)[1]), "+f"((acc)[2]), "+f"((acc)[3]) \
        : "r"(a0), "r"(a1), "r"(a2), "r"(a3), "r"(b0), "r"(b1))

__device__ __forceinline__ float ex2(float x) {
    float r;
    asm("ex2.approx.ftz.f32 %0, %1;" : "=f"(r) : "f"(x));
    return r;
}
__device__ __forceinline__ uint32_t packh2(float x, float y) {
    __half2 h = __floats2half2_rn(x, y);
    return *(uint32_t*)&h;
}

// ---------------- fused prep: x fp32->fp16 (blocks 0..8191) + 4x weight transpose ----------------
__global__ __launch_bounds__(256) void prep(
    const float* __restrict__ x, const float* __restrict__ w0,
    const float* __restrict__ w1, const float* __restrict__ w2,
    const float* __restrict__ w3, __half* __restrict__ x16,
    __half* __restrict__ w4)
{
    __shared__ float t[32][33];
    const int bx = blockIdx.x;
    const int tid = threadIdx.x;
    if (bx < 8192) {
        const int i = bx * 256 + tid;
        float4 v = ((const float4*)x)[i];
        *(__half2*)(x16 + 4 * (size_t)i)     = __floats2half2_rn(v.x, v.y);
        *(__half2*)(x16 + 4 * (size_t)i + 2) = __floats2half2_rn(v.z, v.w);
    } else {
        const int b2 = bx - 8192;
        const int z  = b2 >> 10;
        const float* W = (z == 0) ? w0 : (z == 1) ? w1 : (z == 2) ? w2 : w3;
        __half* Wt = w4 + (size_t)z * D_MODEL * D_MODEL;
        const int n0 = (b2 & 31) * 32;
        const int k0 = ((b2 >> 5) & 31) * 32;
        const int tx = tid & 31, ty = tid >> 5;
        #pragma unroll
        for (int j = 0; j < 32; j += 8)
            t[ty + j][tx] = W[(size_t)(k0 + ty + j) * D_MODEL + n0 + tx];
        __syncthreads();
        #pragma unroll
        for (int j = 0; j < 32; j += 8)
            Wt[(size_t)(n0 + ty + j) * D_MODEL + k0 + tx] = __float2half_rn(t[tx][ty + j]);
    }
}

// ---------------- GEMM core (A[M,K] @ B[N,K]^T, 128x128 tile) ----------------
// 2-stage ring + 3 CTAs/SM (occupancy experiment). Trailing barrier makes
// buffer reuse safe: prefetch of tile kt+1 into buf[(kt+1)&1] is only issued
// after the barrier that ends iteration kt-1 (which read that buffer).
#define TKk 64
#define NKT (D_MODEL / TKk)
#define RSTR 144
#define TILEB (128 * RSTR)
#define STAGEB (2 * TILEB)
#define GEMM_SMEM (2 * STAGEB)   // 73728 -> 3 CTAs/SM

__device__ __forceinline__ void load_stage(
    uint32_t base, const __half* __restrict__ A, const __half* __restrict__ B,
    int m0, int n0, int k0, int tid)
{
    #pragma unroll
    for (int it = 0; it < 4; it++) {
        const int idx = tid + it * 256;
        const int r = idx >> 3;
        const int c = idx & 7;
        const uint32_t so = (uint32_t)(r * RSTR + c * 16);
        CP_ASYNC16(base + so,         A + (size_t)(m0 + r) * D_MODEL + k0 + c * 8);
        CP_ASYNC16(base + TILEB + so, B + (size_t)(n0 + r) * D_MODEL + k0 + c * 8);
    }
}

__device__ __forceinline__ void gemm_core(
    uint32_t smb, const __half* A, const __half* Bw,
    int m0, int n0, int tid, float acc[4][4][4])
{
    const int wid = tid >> 5;
    const int lane = tid & 31;
    const int warp_m = wid & 1;
    const int warp_n = wid >> 1;
    const int lrow = lane & 15;
    const uint32_t lcol = (uint32_t)((lane >> 4) * 16);

    load_stage(smb, A, Bw, m0, n0, 0, tid); CP_COMMIT();

    for (int kt = 0; kt < NKT; kt++) {
        if (kt + 1 < NKT)
            load_stage(smb + (uint32_t)(((kt + 1) & 1) * STAGEB),
                       A, Bw, m0, n0, (kt + 1) * TKk, tid);
        CP_COMMIT();
        CP_WAIT(1);
        __syncthreads();

        const uint32_t st = smb + (uint32_t)((kt & 1) * STAGEB);
        #pragma unroll
        for (int ks = 0; ks < 4; ks++) {
            const uint32_t ko = (uint32_t)(ks * 32) + lcol;
            uint32_t b[2][4], a[4][4];
            #pragma unroll
            for (int p = 0; p < 2; p++)
                LDMX4(b[p][0], b[p][1], b[p][2], b[p][3],
                      st + TILEB + (uint32_t)((warp_n * 32 + p * 16 + lrow) * RSTR) + ko);
            #pragma unroll
            for (int mi = 0; mi < 4; mi++)
                LDMX4(a[mi][0], a[mi][1], a[mi][2], a[mi][3],
                      st + (uint32_t)((warp_m * 64 + mi * 16 + lrow) * RSTR) + ko);
            #pragma unroll
            for (int mi = 0; mi < 4; mi++)
                #pragma unroll
                for (int ni = 0; ni < 4; ni++)
                    MMA16816(acc[mi][ni], a[mi][0], a[mi][1], a[mi][2], a[mi][3],
                             b[ni >> 1][ni & 1], b[ni >> 1][2 + (ni & 1)]);
        }
        __syncthreads();   // all reads of buf[kt&1] done -> safe to overwrite next iter
    }
}

// Fused QKV projection: blockIdx.z = 0(Q) / 1(K) / 2(Vt)
__global__ __launch_bounds__(256, 3) void gemm_qkv(
    const __half* __restrict__ x16, const __half* __restrict__ w4,
    const float* __restrict__ b_q, const float* __restrict__ b_k,
    const float* __restrict__ b_v,
    __half* __restrict__ qq, __half* __restrict__ kk, __half* __restrict__ vt)
{
    extern __shared__ char sm[];
    const uint32_t smb = smem_u32(sm);
    const int tid = threadIdx.x;
    const int z = blockIdx.z;
    const int m0 = blockIdx.y * 128;
    const int n0 = blockIdx.x * 128;
    const __half* Bw = w4 + (size_t)z * D_MODEL * D_MODEL;
    const float* bias = (z == 0) ? b_q : (z == 1) ? b_k : b_v;

    float acc[4][4][4];
    #pragma unroll
    for (int i = 0; i < 4; i++)
        #pragma unroll
        for (int j = 0; j < 4; j++)
            #pragma unroll
            for (int r = 0; r < 4; r++) acc[i][j][r] = 0.f;

    gemm_core(smb, x16, Bw, m0, n0, tid, acc);

    const int wid = tid >> 5;
    const int lane = tid & 31;
    const int g = lane >> 2;
    const int t = lane & 3;
    #pragma unroll
    for (int mi = 0; mi < 4; mi++) {
        #pragma unroll
        for (int ni = 0; ni < 4; ni++) {
            const int n = n0 + (wid >> 1) * 32 + ni * 8 + t * 2;
            const float b0 = bias[n], b1 = bias[n + 1];
            #pragma unroll
            for (int hf = 0; hf < 2; hf++) {
                const int m = m0 + (wid & 1) * 64 + mi * 16 + g + hf * 8;
                const float v0 = acc[mi][ni][hf * 2 + 0] + b0;
                const float v1 = acc[mi][ni][hf * 2 + 1] + b1;
                const int bb = m >> 11, tt = m & (SEQ - 1);
                const int hh = n >> 6, dd = n & (DK - 1);
                if (z == 0) {
                    *(__half2*)(qq + ((size_t)(bb * 16 + hh) * SEQ + tt) * DK + dd)
                        = __floats2half2_rn(v0 * QSCALE, v1 * QSCALE);
                } else if (z == 1) {
                    *(__half2*)(kk + ((size_t)(bb * 16 + hh) * SEQ + tt) * DK + dd)
                        = __floats2half2_rn(v0, v1);
                } else {
                    const size_t idx = ((size_t)(bb * 16 + hh) * DK + dd) * SEQ + tt;
                    vt[idx]       = __float2half_rn(v0);
                    vt[idx + SEQ] = __float2half_rn(v1);
                }
            }
        }
    }
}

// Output projection (fp32 out)
__global__ __launch_bounds__(256, 3) void gemm_oproj(
    const __half* __restrict__ A, const __half* __restrict__ Bw,
    const float* __restrict__ bias, float* __restrict__ out)
{
    extern __shared__ char sm[];
    const uint32_t smb = smem_u32(sm);
    const int tid = threadIdx.x;
    const int m0 = blockIdx.y * 128;
    const int n0 = blockIdx.x * 128;

    float acc[4][4][4];
    #pragma unroll
    for (int i = 0; i < 4; i++)
        #pragma unroll
        for (int j = 0; j < 4; j++)
            #pragma unroll
            for (int r = 0; r < 4; r++) acc[i][j][r] = 0.f;

    gemm_core(smb, A, Bw, m0, n0, tid, acc);

    const int wid = tid >> 5;
    const int lane = tid & 31;
    const int g = lane >> 2;
    const int t = lane & 3;
    #pragma unroll
    for (int mi = 0; mi < 4; mi++) {
        #pragma unroll
        for (int ni = 0; ni < 4; ni++) {
            const int n = n0 + (wid >> 1) * 32 + ni * 8 + t * 2;
            const float b0 = bias[n], b1 = bias[n + 1];
            #pragma unroll
            for (int hf = 0; hf < 2; hf++) {
                const int m = m0 + (wid & 1) * 64 + mi * 16 + g + hf * 8;
                *(float2*)(out + (size_t)m * D_MODEL + n)
                    = make_float2(acc[mi][ni][hf * 2 + 0] + b0,
                                  acc[mi][ni][hf * 2 + 1] + b1);
            }
        }
    }
}

// ---------------- FlashAttention-2 on HMMA, 3-stage KV ring, base-2 softmax ----------------
#define BQ 128
#define BKV 64
#define ASTR 144
#define QTILE (BQ * ASTR)
#define KVTILE (BKV * ASTR)
#define KVBUF (2 * KVTILE)
#define ATTN_SMEM (QTILE + 3 * KVBUF)   // 73728

__device__ __forceinline__ void attn_load_kv(
    uint32_t base, const __half* __restrict__ Kg, const __half* __restrict__ Vtg,
    size_t bhoff, int k0, int tid)
{
    #pragma unroll
    for (int it = 0; it < 2; it++) {
        const int i = tid + it * 256;
        const int r = i >> 3;
        const int c = i & 7;
        const uint32_t so = (uint32_t)(r * ASTR + c * 16);
        CP_ASYNC16(base + so,          Kg  + bhoff + (size_t)(k0 + r) * DK + c * 8);
        CP_ASYNC16(base + KVTILE + so, Vtg + bhoff + (size_t)r * SEQ + k0 + c * 8);
    }
}

__global__ __launch_bounds__(256) void attn_hmma(
    const __half* __restrict__ Qg, const __half* __restrict__ Kg,
    const __half* __restrict__ Vtg, __half* __restrict__ Og)
{
    extern __shared__ char sm[];
    const uint32_t smb = smem_u32(sm);
    const int tid = threadIdx.x;
    const int wid = tid >> 5;
    const int lane = tid & 31;
    const int qb = gridDim.x - 1 - blockIdx.x;
    const int bh = blockIdx.y;
    const int q0 = qb * BQ;
    const size_t bhoff = (size_t)bh * SEQ * DK;
    const int lrow = lane & 15;
    const uint32_t lcol = (uint32_t)((lane >> 4) * 16);
    const int g = lane >> 2;
    const int t = lane & 3;
    const int q0w = q0 + wid * 16;
    const uint32_t kvb = smb + QTILE;
    const int nt = qb * 2 + 2;

    #pragma unroll
    for (int it = 0; it < 4; it++) {
        const int i = tid + it * 256;
        const int r = i >> 3;
        const int c = i & 7;
        CP_ASYNC16(smb + (uint32_t)(r * ASTR + c * 16),
                   Qg + bhoff + (size_t)(q0 + r) * DK + c * 8);
    }
    attn_load_kv(kvb, Kg, Vtg, bhoff, 0, tid);
    CP_COMMIT();
    attn_load_kv(kvb + KVBUF, Kg, Vtg, bhoff, BKV, tid);
    CP_COMMIT();

    uint32_t qf[4][4];
    float oacc[8][4];
    #pragma unroll
    for (int f = 0; f < 8; f++)
        #pragma unroll
        for (int r = 0; r < 4; r++) oacc[f][r] = 0.f;
    float m_i[2] = {-1e30f, -1e30f};
    float l_i[2] = {0.f, 0.f};

    int stage = 0;
    for (int kt = 0; kt < nt; kt++) {
        const int k0 = kt * BKV;
        CP_WAIT(1);
        __syncthreads();
        if (kt + 2 < nt) {
            int ns = stage + 2; if (ns >= 3) ns -= 3;
            attn_load_kv(kvb + (uint32_t)(ns * KVBUF), Kg, Vtg, bhoff, k0 + 2 * BKV, tid);
        }
        CP_COMMIT();

        if (kt == 0) {
            #pragma unroll
            for (int kf = 0; kf < 4; kf++) {
                const uint32_t ro = (uint32_t)((wid * 16 + lrow) * ASTR) + (uint32_t)(kf * 32) + lcol;
                LDMX4(qf[kf][0], qf[kf][1], qf[kf][2], qf[kf][3], smb + ro);
            }
        }

        if (q0w + 15 >= k0) {
            const uint32_t kb = kvb + (uint32_t)(stage * KVBUF);
            const uint32_t vb = kb + KVTILE;

            float s[8][4];
            #pragma unroll
            for (int f = 0; f < 8; f++)
                #pragma unroll
                for (int r = 0; r < 4; r++) s[f][r] = 0.f;

            #pragma unroll
            for (int kf = 0; kf < 4; kf++) {
                const uint32_t ko = (uint32_t)(kf * 32) + lcol;
                #pragma unroll
                for (int p = 0; p < 4; p++) {
                    uint32_t b0, b1, b2, b3;
                    LDMX4(b0, b1, b2, b3, kb + (uint32_t)((p * 16 + lrow) * ASTR) + ko);
                    MMA16816(s[2*p],   qf[kf][0], qf[kf][1], qf[kf][2], qf[kf][3], b0, b2);
                    MMA16816(s[2*p+1], qf[kf][0], qf[kf][1], qf[kf][2], qf[kf][3], b1, b3);
                }
            }

            if (k0 + 63 > q0w) {
                const int r0 = q0w + g, r1 = r0 + 8;
                #pragma unroll
                for (int ni = 0; ni < 8; ni++) {
                    const int c0 = k0 + ni * 8 + t * 2;
                    if (c0     > r0) s[ni][0] = -1e30f;
                    if (c0 + 1 > r0) s[ni][1] = -1e30f;
                    if (c0     > r1) s[ni][2] = -1e30f;
                    if (c0 + 1 > r1) s[ni][3] = -1e30f;
                }
            }

            float rmx0 = -1e30f, rmx1 = -1e30f;
            #pragma unroll
            for (int ni = 0; ni < 8; ni++) {
                rmx0 = fmaxf(rmx0, fmaxf(s[ni][0], s[ni][1]));
                rmx1 = fmaxf(rmx1, fmaxf(s[ni][2], s[ni][3]));
            }
            rmx0 = fmaxf(rmx0, __shfl_xor_sync(0xffffffffu, rmx0, 1));
            rmx0 = fmaxf(rmx0, __shfl_xor_sync(0xffffffffu, rmx0, 2));
            rmx1 = fmaxf(rmx1, __shfl_xor_sync(0xffffffffu, rmx1, 1));
            rmx1 = fmaxf(rmx1, __shfl_xor_sync(0xffffffffu, rmx1, 2));
            const float mn0 = fmaxf(m_i[0], rmx0);
            const float mn1 = fmaxf(m_i[1], rmx1);
            const float sc0 = ex2(m_i[0] - mn0);
            const float sc1 = ex2(m_i[1] - mn1);
            float rs0 = 0.f, rs1 = 0.f;
            #pragma unroll
            for (int ni = 0; ni < 8; ni++) {
                s[ni][0] = ex2(s[ni][0] - mn0); rs0 += s[ni][0];
                s[ni][1] = ex2(s[ni][1] - mn0); rs0 += s[ni][1];
                s[ni][2] = ex2(s[ni][2] - mn1); rs1 += s[ni][2];
                s[ni][3] = ex2(s[ni][3] - mn1); rs1 += s[ni][3];
            }
            rs0 += __shfl_xor_sync(0xffffffffu, rs0, 1);
            rs0 += __shfl_xor_sync(0xffffffffu, rs0, 2);
            rs1 += __shfl_xor_sync(0xffffffffu, rs1, 1);
            rs1 += __shfl_xor_sync(0xffffffffu, rs1, 2);
            m_i[0] = mn0; m_i[1] = mn1;
            l_i[0] = l_i[0] * sc0 + rs0;
            l_i[1] = l_i[1] * sc1 + rs1;
            #pragma unroll
            for (int f = 0; f < 8; f++) {
                oacc[f][0] *= sc0; oacc[f][1] *= sc0;
                oacc[f][2] *= sc1; oacc[f][3] *= sc1;
            }

            #pragma unroll
            for (int kf = 0; kf < 4; kf++) {
                const uint32_t pa0 = packh2(s[2*kf][0],   s[2*kf][1]);
                const uint32_t pa1 = packh2(s[2*kf][2],   s[2*kf][3]);
                const uint32_t pa2 = packh2(s[2*kf+1][0], s[2*kf+1][1]);
                const uint32_t pa3 = packh2(s[2*kf+1][2], s[2*kf+1][3]);
                const uint32_t ko = (uint32_t)(kf * 32) + lcol;
                #pragma unroll
                for (int p = 0; p < 4; p++) {
                    uint32_t b0, b1, b2, b3;
                    LDMX4(b0, b1, b2, b3, vb + (uint32_t)((p * 16 + lrow) * ASTR) + ko);
                    MMA16816(oacc[2*p],   pa0, pa1, pa2, pa3, b0, b2);
                    MMA16816(oacc[2*p+1], pa0, pa1, pa2, pa3, b1, b3);
                }
            }
        }
        if (++stage >= 3) stage = 0;
    }

    const float inv0 = 1.0f / l_i[0];
    const float inv1 = 1.0f / l_i[1];
    const int b = bh >> 4, h = bh & 15;
    const int r0 = q0w + g, r1 = r0 + 8;
    #pragma unroll
    for (int ni = 0; ni < 8; ni++) {
        const int col = h * 64 + ni * 8 + t * 2;
        *(__half2*)(Og + (size_t)(b * SEQ + r0) * D_MODEL + col)
            = __floats2half2_rn(oacc[ni][0] * inv0, oacc[ni][1] * inv0);
        *(__half2*)(Og + (size_t)(b * SEQ + r1) * D_MODEL + col)
            = __floats2half2_rn(oacc[ni][2] * inv1, oacc[ni][3] * inv1);
    }
}

// ---------------------------------------------------------------------------
extern "C" void kernel_launch(void* const* d_in, const int* in_sizes, int n_in,
                              void* d_out, int out_size)
{
    const float* x   = (const float*)d_in[0];
    const float* w_q = (const float*)d_in[2];
    const float* b_q = (const float*)d_in[3];
    const float* w_k = (const float*)d_in[4];
    const float* b_k = (const float*)d_in[5];
    const float* w_v = (const float*)d_in[6];
    const float* b_v = (const float*)d_in[7];
    const float* w_o = (const float*)d_in[8];
    const float* b_o = (const float*)d_in[9];
    float* out = (float*)d_out;

    __half *x16, *w4, *qq, *kk, *vt, *oo;
    cudaGetSymbolAddress((void**)&x16, g_x16);
    cudaGetSymbolAddress((void**)&w4, g_w4);
    cudaGetSymbolAddress((void**)&qq, g_q);
    cudaGetSymbolAddress((void**)&kk, g_k);
    cudaGetSymbolAddress((void**)&vt, g_vt);
    cudaGetSymbolAddress((void**)&oo, g_o);

    const size_t WSZ = (size_t)D_MODEL * D_MODEL;
    __half *wo = w4 + 3 * WSZ;

    cudaFuncSetAttribute(gemm_qkv,   cudaFuncAttributeMaxDynamicSharedMemorySize, GEMM_SMEM);
    cudaFuncSetAttribute(gemm_oproj, cudaFuncAttributeMaxDynamicSharedMemorySize, GEMM_SMEM);
    cudaFuncSetAttribute(attn_hmma,  cudaFuncAttributeMaxDynamicSharedMemorySize, ATTN_SMEM);

    prep<<<8192 + 4096, 256>>>(x, w_q, w_k, w_v, w_o, x16, w4);

    gemm_qkv<<<dim3(D_MODEL / 128, M_ROWS / 128, 3), 256, GEMM_SMEM>>>(
        x16, w4, b_q, b_k, b_v, qq, kk, vt);

    attn_hmma<<<dim3(SEQ / BQ, 64), 256, ATTN_SMEM>>>(qq, kk, vt, oo);

    gemm_oproj<<<dim3(D_MODEL / 128, M_ROWS / 128), 256, GEMM_SMEM>>>(oo, wo, b_o, out);
}

// round 12
// speedup vs baseline: 1.3378x; 1.3378x over previous
#include <cuda_runtime.h>
#include <cuda_fp16.h>
#include <cstdint>
#include <cstddef>

#define D_MODEL 1024
#define N_HEADS 16
#define BATCH   4
#define SEQ     2048
#define DK      64
#define M_ROWS  (BATCH * SEQ)
#define BHT     (64 * SEQ * DK)

// Q pre-scale: (1/sqrt(dk)) * log2(e) so softmax uses raw ex2
#define QSCALE 0.18033688011112042f

__device__ __half g_x16[M_ROWS * D_MODEL];
__device__ __half g_w4[4 * D_MODEL * D_MODEL];
__device__ __half g_q [BHT];            // [bh][t][dk], pre-scaled by QSCALE
__device__ __half g_k [BHT];            // [bh][t][dk]
__device__ __half g_vt[BHT];            // [bh][dk][t]
__device__ __half g_o [M_ROWS * D_MODEL];

__device__ __forceinline__ uint32_t smem_u32(const void* p) {
    uint32_t a;
    asm("{ .reg .u64 t; cvta.to.shared.u64 t, %1; cvt.u32.u64 %0, t; }" : "=r"(a) : "l"(p));
    return a;
}
#define CP_ASYNC16(dst, src) \
    asm volatile("cp.async.cg.shared.global [%0], [%1], 16;" :: "r"(dst), "l"(src))
#define CP_COMMIT()  asm volatile("cp.async.commit_group;" ::: "memory")
#define CP_WAIT(n)   asm volatile("cp.async.wait_group %0;" :: "n"(n) : "memory")
#define LDMX4(r0, r1, r2, r3, addr) \
    asm volatile("ldmatrix.sync.aligned.m8n8.x4.shared.b16 {%0,%1,%2,%3}, [%4];" \
        : "=r"(r0), "=r"(r1), "=r"(r2), "=r"(r3) : "r"(addr))
#define MMA16816(acc, a0, a1, a2, a3, b0, b1) \
    asm volatile("mma.sync.aligned.m16n8k16.row.col.f32.f16.f16.f32 " \
        "{%0,%1,%2,%3},{%4,%5,%6,%7},{%8,%9},{%0,%1,%2,%3};" \
        : "+f"((acc)[0]), "+f"((acc)[1]), "+f"((acc)[2]), "+f"((acc)[3]) \
        : "r"(a0), "r"(a1), "r"(a2), "r"(a3), "r"(b0), "r"(b1))

__device__ __forceinline__ float ex2(float x) {
    float r;
    asm("ex2.approx.ftz.f32 %0, %1;" : "=f"(r) : "f"(x));
    return r;
}
__device__ __forceinline__ uint32_t packh2(float x, float y) {
    __half2 h = __floats2half2_rn(x, y);
    return *(uint32_t*)&h;
}

// ---------------- fused prep: x fp32->fp16 (blocks 0..8191) + 4x weight transpose ----------------
__global__ __launch_bounds__(256) void prep(
    const float* __restrict__ x, const float* __restrict__ w0,
    const float* __restrict__ w1, const float* __restrict__ w2,
    const float* __restrict__ w3, __half* __restrict__ x16,
    __half* __restrict__ w4)
{
    __shared__ float t[32][33];
    const int bx = blockIdx.x;
    const int tid = threadIdx.x;
    if (bx < 8192) {
        const int i = bx * 256 + tid;   // n4 = 2M, exactly 8192*256
        float4 v = ((const float4*)x)[i];
        *(__half2*)(x16 + 4 * (size_t)i)     = __floats2half2_rn(v.x, v.y);
        *(__half2*)(x16 + 4 * (size_t)i + 2) = __floats2half2_rn(v.z, v.w);
    } else {
        const int b2 = bx - 8192;               // 0..4095
        const int z  = b2 >> 10;                // weight index
        const float* W = (z == 0) ? w0 : (z == 1) ? w1 : (z == 2) ? w2 : w3;
        __half* Wt = w4 + (size_t)z * D_MODEL * D_MODEL;
        const int n0 = (b2 & 31) * 32;
        const int k0 = ((b2 >> 5) & 31) * 32;
        const int tx = tid & 31, ty = tid >> 5; // ty 0..7
        #pragma unroll
        for (int j = 0; j < 32; j += 8)
            t[ty + j][tx] = W[(size_t)(k0 + ty + j) * D_MODEL + n0 + tx];
        __syncthreads();
        #pragma unroll
        for (int j = 0; j < 32; j += 8)
            Wt[(size_t)(n0 + ty + j) * D_MODEL + k0 + tx] = __float2half_rn(t[tx][ty + j]);
    }
}

// ---------------- GEMM core (A[M,K] @ B[N,K]^T, 128x128 tile) ----------------
#define TKk 64
#define NKT (D_MODEL / TKk)
#define RSTR 144
#define TILEB (128 * RSTR)
#define STAGEB (2 * TILEB)
#define NSTAGE 3
#define GEMM_SMEM (NSTAGE * STAGEB)  // 110592 -> 2 CTAs/SM, full reg budget

__device__ __forceinline__ void load_stage(
    uint32_t base, const __half* __restrict__ A, const __half* __restrict__ B,
    int m0, int n0, int k0, int tid)
{
    #pragma unroll
    for (int it = 0; it < 4; it++) {
        const int idx = tid + it * 256;
        const int r = idx >> 3;
        const int c = idx & 7;
        const uint32_t so = (uint32_t)(r * RSTR + c * 16);
        CP_ASYNC16(base + so,         A + (size_t)(m0 + r) * D_MODEL + k0 + c * 8);
        CP_ASYNC16(base + TILEB + so, B + (size_t)(n0 + r) * D_MODEL + k0 + c * 8);
    }
}

__device__ __forceinline__ void gemm_core(
    uint32_t smb, const __half* A, const __half* Bw,
    int m0, int n0, int tid, float acc[4][4][4])
{
    const int wid = tid >> 5;
    const int lane = tid & 31;
    const int warp_m = wid & 1;
    const int warp_n = wid >> 1;
    const int lrow = lane & 15;
    const uint32_t lcol = (uint32_t)((lane >> 4) * 16);

    load_stage(smb,          A, Bw, m0, n0, 0,   tid); CP_COMMIT();
    load_stage(smb + STAGEB, A, Bw, m0, n0, TKk, tid); CP_COMMIT();

    int stage = 0;
    for (int kt = 0; kt < NKT; kt++) {
        CP_WAIT(1);
        __syncthreads();
        if (kt + 2 < NKT) {
            int ns = stage + 2; if (ns >= NSTAGE) ns -= NSTAGE;
            load_stage(smb + (uint32_t)(ns * STAGEB), A, Bw, m0, n0, (kt + 2) * TKk, tid);
        }
        CP_COMMIT();

        const uint32_t st = smb + (uint32_t)(stage * STAGEB);
        #pragma unroll
        for (int ks = 0; ks < 4; ks++) {
            const uint32_t ko = (uint32_t)(ks * 32) + lcol;
            uint32_t b[2][4], a[4][4];
            #pragma unroll
            for (int p = 0; p < 2; p++)
                LDMX4(b[p][0], b[p][1], b[p][2], b[p][3],
                      st + TILEB + (uint32_t)((warp_n * 32 + p * 16 + lrow) * RSTR) + ko);
            #pragma unroll
            for (int mi = 0; mi < 4; mi++)
                LDMX4(a[mi][0], a[mi][1], a[mi][2], a[mi][3],
                      st + (uint32_t)((warp_m * 64 + mi * 16 + lrow) * RSTR) + ko);
            #pragma unroll
            for (int mi = 0; mi < 4; mi++)
                #pragma unroll
                for (int ni = 0; ni < 4; ni++)
                    MMA16816(acc[mi][ni], a[mi][0], a[mi][1], a[mi][2], a[mi][3],
                             b[ni >> 1][ni & 1], b[ni >> 1][2 + (ni & 1)]);
        }
        if (++stage >= NSTAGE) stage = 0;
    }
}

// Fused QKV projection: blockIdx.z = 0(Q) / 1(K) / 2(Vt)
__global__ __launch_bounds__(256) void gemm_qkv(
    const __half* __restrict__ x16, const __half* __restrict__ w4,
    const float* __restrict__ b_q, const float* __restrict__ b_k,
    const float* __restrict__ b_v,
    __half* __restrict__ qq, __half* __restrict__ kk, __half* __restrict__ vt)
{
    extern __shared__ char sm[];
    const uint32_t smb = smem_u32(sm);
    const int tid = threadIdx.x;
    const int z = blockIdx.z;
    const int m0 = blockIdx.y * 128;
    const int n0 = blockIdx.x * 128;
    const __half* Bw = w4 + (size_t)z * D_MODEL * D_MODEL;
    const float* bias = (z == 0) ? b_q : (z == 1) ? b_k : b_v;

    float acc[4][4][4];
    #pragma unroll
    for (int i = 0; i < 4; i++)
        #pragma unroll
        for (int j = 0; j < 4; j++)
            #pragma unroll
            for (int r = 0; r < 4; r++) acc[i][j][r] = 0.f;

    gemm_core(smb, x16, Bw, m0, n0, tid, acc);

    const int wid = tid >> 5;
    const int lane = tid & 31;
    const int g = lane >> 2;
    const int t = lane & 3;
    #pragma unroll
    for (int mi = 0; mi < 4; mi++) {
        #pragma unroll
        for (int ni = 0; ni < 4; ni++) {
            const int n = n0 + (wid >> 1) * 32 + ni * 8 + t * 2;
            const float b0 = bias[n], b1 = bias[n + 1];
            #pragma unroll
            for (int hf = 0; hf < 2; hf++) {
                const int m = m0 + (wid & 1) * 64 + mi * 16 + g + hf * 8;
                const float v0 = acc[mi][ni][hf * 2 + 0] + b0;
                const float v1 = acc[mi][ni][hf * 2 + 1] + b1;
                const int bb = m >> 11, tt = m & (SEQ - 1);
                const int hh = n >> 6, dd = n & (DK - 1);
                if (z == 0) {
                    *(__half2*)(qq + ((size_t)(bb * 16 + hh) * SEQ + tt) * DK + dd)
                        = __floats2half2_rn(v0 * QSCALE, v1 * QSCALE);
                } else if (z == 1) {
                    *(__half2*)(kk + ((size_t)(bb * 16 + hh) * SEQ + tt) * DK + dd)
                        = __floats2half2_rn(v0, v1);
                } else {
                    const size_t idx = ((size_t)(bb * 16 + hh) * DK + dd) * SEQ + tt;
                    vt[idx]       = __float2half_rn(v0);
                    vt[idx + SEQ] = __float2half_rn(v1);
                }
            }
        }
    }
}

// Output projection (fp32 out)
__global__ __launch_bounds__(256) void gemm_oproj(
    const __half* __restrict__ A, const __half* __restrict__ Bw,
    const float* __restrict__ bias, float* __restrict__ out)
{
    extern __shared__ char sm[];
    const uint32_t smb = smem_u32(sm);
    const int tid = threadIdx.x;
    const int m0 = blockIdx.y * 128;
    const int n0 = blockIdx.x * 128;

    float acc[4][4][4];
    #pragma unroll
    for (int i = 0; i < 4; i++)
        #pragma unroll
        for (int j = 0; j < 4; j++)
            #pragma unroll
            for (int r = 0; r < 4; r++) acc[i][j][r] = 0.f;

    gemm_core(smb, A, Bw, m0, n0, tid, acc);

    const int wid = tid >> 5;
    const int lane = tid & 31;
    const int g = lane >> 2;
    const int t = lane & 3;
    #pragma unroll
    for (int mi = 0; mi < 4; mi++) {
        #pragma unroll
        for (int ni = 0; ni < 4; ni++) {
            const int n = n0 + (wid >> 1) * 32 + ni * 8 + t * 2;
            const float b0 = bias[n], b1 = bias[n + 1];
            #pragma unroll
            for (int hf = 0; hf < 2; hf++) {
                const int m = m0 + (wid & 1) * 64 + mi * 16 + g + hf * 8;
                *(float2*)(out + (size_t)m * D_MODEL + n)
                    = make_float2(acc[mi][ni][hf * 2 + 0] + b0,
                                  acc[mi][ni][hf * 2 + 1] + b1);
            }
        }
    }
}

// ---------------- FlashAttention-2 on HMMA, 3-stage KV ring, base-2 softmax ----------------
#define BQ 128
#define BKV 64
#define ASTR 144
#define QTILE (BQ * ASTR)
#define KVTILE (BKV * ASTR)
#define KVBUF (2 * KVTILE)
#define ATTN_SMEM (QTILE + 3 * KVBUF)   // 73728

__device__ __forceinline__ void attn_load_kv(
    uint32_t base, const __half* __restrict__ Kg, const __half* __restrict__ Vtg,
    size_t bhoff, int k0, int tid)
{
    #pragma unroll
    for (int it = 0; it < 2; it++) {
        const int i = tid + it * 256;
        const int r = i >> 3;
        const int c = i & 7;
        const uint32_t so = (uint32_t)(r * ASTR + c * 16);
        CP_ASYNC16(base + so,          Kg  + bhoff + (size_t)(k0 + r) * DK + c * 8);
        CP_ASYNC16(base + KVTILE + so, Vtg + bhoff + (size_t)r * SEQ + k0 + c * 8);
    }
}

__global__ __launch_bounds__(256) void attn_hmma(
    const __half* __restrict__ Qg, const __half* __restrict__ Kg,
    const __half* __restrict__ Vtg, __half* __restrict__ Og)
{
    extern __shared__ char sm[];
    const uint32_t smb = smem_u32(sm);
    const int tid = threadIdx.x;
    const int wid = tid >> 5;
    const int lane = tid & 31;
    const int qb = gridDim.x - 1 - blockIdx.x;
    const int bh = blockIdx.y;
    const int q0 = qb * BQ;
    const size_t bhoff = (size_t)bh * SEQ * DK;
    const int lrow = lane & 15;
    const uint32_t lcol = (uint32_t)((lane >> 4) * 16);
    const int g = lane >> 2;
    const int t = lane & 3;
    const int q0w = q0 + wid * 16;
    const uint32_t kvb = smb + QTILE;
    const int nt = qb * 2 + 2;

    #pragma unroll
    for (int it = 0; it < 4; it++) {
        const int i = tid + it * 256;
        const int r = i >> 3;
        const int c = i & 7;
        CP_ASYNC16(smb + (uint32_t)(r * ASTR + c * 16),
                   Qg + bhoff + (size_t)(q0 + r) * DK + c * 8);
    }
    attn_load_kv(kvb, Kg, Vtg, bhoff, 0, tid);
    CP_COMMIT();
    attn_load_kv(kvb + KVBUF, Kg, Vtg, bhoff, BKV, tid);
    CP_COMMIT();

    uint32_t qf[4][4];
    float oacc[8][4];
    #pragma unroll
    for (int f = 0; f < 8; f++)
        #pragma unroll
        for (int r = 0; r < 4; r++) oacc[f][r] = 0.f;
    float m_i[2] = {-1e30f, -1e30f};
    float l_i[2] = {0.f, 0.f};

    int stage = 0;
    for (int kt = 0; kt < nt; kt++) {
        const int k0 = kt * BKV;
        CP_WAIT(1);
        __syncthreads();
        if (kt + 2 < nt) {
            int ns = stage + 2; if (ns >= 3) ns -= 3;
            attn_load_kv(kvb + (uint32_t)(ns * KVBUF), Kg, Vtg, bhoff, k0 + 2 * BKV, tid);
        }
        CP_COMMIT();

        if (kt == 0) {
            #pragma unroll
            for (int kf = 0; kf < 4; kf++) {
                const uint32_t ro = (uint32_t)((wid * 16 + lrow) * ASTR) + (uint32_t)(kf * 32) + lcol;
                LDMX4(qf[kf][0], qf[kf][1], qf[kf][2], qf[kf][3], smb + ro);
            }
        }

        if (q0w + 15 >= k0) {
            const uint32_t kb = kvb + (uint32_t)(stage * KVBUF);
            const uint32_t vb = kb + KVTILE;

            float s[8][4];
            #pragma unroll
            for (int f = 0; f < 8; f++)
                #pragma unroll
                for (int r = 0; r < 4; r++) s[f][r] = 0.f;

            #pragma unroll
            for (int kf = 0; kf < 4; kf++) {
                const uint32_t ko = (uint32_t)(kf * 32) + lcol;
                #pragma unroll
                for (int p = 0; p < 4; p++) {
                    uint32_t b0, b1, b2, b3;
                    LDMX4(b0, b1, b2, b3, kb + (uint32_t)((p * 16 + lrow) * ASTR) + ko);
                    MMA16816(s[2*p],   qf[kf][0], qf[kf][1], qf[kf][2], qf[kf][3], b0, b2);
                    MMA16816(s[2*p+1], qf[kf][0], qf[kf][1], qf[kf][2], qf[kf][3], b1, b3);
                }
            }

            if (k0 + 63 > q0w) {
                const int r0 = q0w + g, r1 = r0 + 8;
                #pragma unroll
                for (int ni = 0; ni < 8; ni++) {
                    const int c0 = k0 + ni * 8 + t * 2;
                    if (c0     > r0) s[ni][0] = -1e30f;
                    if (c0 + 1 > r0) s[ni][1] = -1e30f;
                    if (c0     > r1) s[ni][2] = -1e30f;
                    if (c0 + 1 > r1) s[ni][3] = -1e30f;
                }
            }

            float rmx0 = -1e30f, rmx1 = -1e30f;
            #pragma unroll
            for (int ni = 0; ni < 8; ni++) {
                rmx0 = fmaxf(rmx0, fmaxf(s[ni][0], s[ni][1]));
                rmx1 = fmaxf(rmx1, fmaxf(s[ni][2], s[ni][3]));
            }
            rmx0 = fmaxf(rmx0, __shfl_xor_sync(0xffffffffu, rmx0, 1));
            rmx0 = fmaxf(rmx0, __shfl_xor_sync(0xffffffffu, rmx0, 2));
            rmx1 = fmaxf(rmx1, __shfl_xor_sync(0xffffffffu, rmx1, 1));
            rmx1 = fmaxf(rmx1, __shfl_xor_sync(0xffffffffu, rmx1, 2));
            const float mn0 = fmaxf(m_i[0], rmx0);
            const float mn1 = fmaxf(m_i[1], rmx1);
            const float sc0 = ex2(m_i[0] - mn0);
            const float sc1 = ex2(m_i[1] - mn1);
            float rs0 = 0.f, rs1 = 0.f;
            #pragma unroll
            for (int ni = 0; ni < 8; ni++) {
                s[ni][0] = ex2(s[ni][0] - mn0); rs0 += s[ni][0];
                s[ni][1] = ex2(s[ni][1] - mn0); rs0 += s[ni][1];
                s[ni][2] = ex2(s[ni][2] - mn1); rs1 += s[ni][2];
                s[ni][3] = ex2(s[ni][3] - mn1); rs1 += s[ni][3];
            }
            rs0 += __shfl_xor_sync(0xffffffffu, rs0, 1);
            rs0 += __shfl_xor_sync(0xffffffffu, rs0, 2);
            rs1 += __shfl_xor_sync(0xffffffffu, rs1, 1);
            rs1 += __shfl_xor_sync(0xffffffffu, rs1, 2);
            m_i[0] = mn0; m_i[1] = mn1;
            l_i[0] = l_i[0] * sc0 + rs0;
            l_i[1] = l_i[1] * sc1 + rs1;
            #pragma unroll
            for (int f = 0; f < 8; f++) {
                oacc[f][0] *= sc0; oacc[f][1] *= sc0;
                oacc[f][2] *= sc1; oacc[f][3] *= sc1;
            }

            #pragma unroll
            for (int kf = 0; kf < 4; kf++) {
                const uint32_t pa0 = packh2(s[2*kf][0],   s[2*kf][1]);
                const uint32_t pa1 = packh2(s[2*kf][2],   s[2*kf][3]);
                const uint32_t pa2 = packh2(s[2*kf+1][0], s[2*kf+1][1]);
                const uint32_t pa3 = packh2(s[2*kf+1][2], s[2*kf+1][3]);
                const uint32_t ko = (uint32_t)(kf * 32) + lcol;
                #pragma unroll
                for (int p = 0; p < 4; p++) {
                    uint32_t b0, b1, b2, b3;
                    LDMX4(b0, b1, b2, b3, vb + (uint32_t)((p * 16 + lrow) * ASTR) + ko);
                    MMA16816(oacc[2*p],   pa0, pa1, pa2, pa3, b0, b2);
                    MMA16816(oacc[2*p+1], pa0, pa1, pa2, pa3, b1, b3);
                }
            }
        }
        if (++stage >= 3) stage = 0;
    }

    const float inv0 = 1.0f / l_i[0];
    const float inv1 = 1.0f / l_i[1];
    const int b = bh >> 4, h = bh & 15;
    const int r0 = q0w + g, r1 = r0 + 8;
    #pragma unroll
    for (int ni = 0; ni < 8; ni++) {
        const int col = h * 64 + ni * 8 + t * 2;
        *(__half2*)(Og + (size_t)(b * SEQ + r0) * D_MODEL + col)
            = __floats2half2_rn(oacc[ni][0] * inv0, oacc[ni][1] * inv0);
        *(__half2*)(Og + (size_t)(b * SEQ + r1) * D_MODEL + col)
            = __floats2half2_rn(oacc[ni][2] * inv1, oacc[ni][3] * inv1);
    }
}

// ---------------------------------------------------------------------------
extern "C" void kernel_launch(void* const* d_in, const int* in_sizes, int n_in,
                              void* d_out, int out_size)
{
    const float* x   = (const float*)d_in[0];
    const float* w_q = (const float*)d_in[2];
    const float* b_q = (const float*)d_in[3];
    const float* w_k = (const float*)d_in[4];
    const float* b_k = (const float*)d_in[5];
    const float* w_v = (const float*)d_in[6];
    const float* b_v = (const float*)d_in[7];
    const float* w_o = (const float*)d_in[8];
    const float* b_o = (const float*)d_in[9];
    float* out = (float*)d_out;

    __half *x16, *w4, *qq, *kk, *vt, *oo;
    cudaGetSymbolAddress((void**)&x16, g_x16);
    cudaGetSymbolAddress((void**)&w4, g_w4);
    cudaGetSymbolAddress((void**)&qq, g_q);
    cudaGetSymbolAddress((void**)&kk, g_k);
    cudaGetSymbolAddress((void**)&vt, g_vt);
    cudaGetSymbolAddress((void**)&oo, g_o);

    const size_t WSZ = (size_t)D_MODEL * D_MODEL;
    __half *wo = w4 + 3 * WSZ;

    cudaFuncSetAttribute(gemm_qkv,   cudaFuncAttributeMaxDynamicSharedMemorySize, GEMM_SMEM);
    cudaFuncSetAttribute(gemm_oproj, cudaFuncAttributeMaxDynamicSharedMemorySize, GEMM_SMEM);
    cudaFuncSetAttribute(attn_hmma,  cudaFuncAttributeMaxDynamicSharedMemorySize, ATTN_SMEM);

    prep<<<8192 + 4096, 256>>>(x, w_q, w_k, w_v, w_o, x16, w4);

    gemm_qkv<<<dim3(D_MODEL / 128, M_ROWS / 128, 3), 256, GEMM_SMEM>>>(
        x16, w4, b_q, b_k, b_v, qq, kk, vt);

    attn_hmma<<<dim3(SEQ / BQ, 64), 256, ATTN_SMEM>>>(qq, kk, vt, oo);

    gemm_oproj<<<dim3(D_MODEL / 128, M_ROWS / 128), 256, GEMM_SMEM>>>(oo, wo, b_o, out);
}